// round 2
// baseline (speedup 1.0000x reference)
#include <cuda_runtime.h>
#include <cstdint>
#include <cstddef>

// ---------------- problem constants ----------------
#define NU 20000
#define NV 20000
#define NE 320000
#define CU 256
#define CV 256
#define CE 64
#define OU 256
#define OV 256
#define OE 64
#define DU 896   // CU + 2*CV + 2*CE
#define DV 896
#define BN_EPS 1e-5f
#define NEG_BIG (-3.402823466e+38f)

// ---------------- scratch layout (single __device__ arena) ----------------
// sizes in bytes, all 256-aligned
static constexpr size_t SZ_HU   = (size_t)NU * DU * 4;       // 71,680,000
static constexpr size_t SZ_HV   = (size_t)NV * DV * 4;
static constexpr size_t SZ_P    = (size_t)NU * 64 * 4;       // 5,120,000
static constexpr size_t SZ_L    = (size_t)NU * 4;            // 80,000
static constexpr size_t SZ_CNT  = (size_t)NU * 4;
static constexpr size_t SZ_OFF  = 80128;                      // 20001 ints padded
static constexpr size_t SZ_EID  = (size_t)NE * 4;            // 1,280,000
static constexpr size_t SZ_RED  = 256;
static constexpr size_t SZ_STAT = 16384;

static constexpr size_t OFF_HU   = 0;
static constexpr size_t OFF_HV   = OFF_HU + SZ_HU;
static constexpr size_t OFF_PU   = OFF_HV + SZ_HV;
static constexpr size_t OFF_PV   = OFF_PU + SZ_P;
static constexpr size_t OFF_LU   = OFF_PV + SZ_P;
static constexpr size_t OFF_LV   = OFF_LU + SZ_L;
static constexpr size_t OFF_WU   = OFF_LV + SZ_L;
static constexpr size_t OFF_WV   = OFF_WU + SZ_L;
static constexpr size_t OFF_CNTU = OFF_WV + SZ_L;
static constexpr size_t OFF_CNTV = OFF_CNTU + SZ_CNT;
static constexpr size_t OFF_OFFU = OFF_CNTV + SZ_CNT;
static constexpr size_t OFF_OFFV = OFF_OFFU + SZ_OFF;
static constexpr size_t OFF_CURU = OFF_OFFV + SZ_OFF;
static constexpr size_t OFF_CURV = OFF_CURU + SZ_CNT;
static constexpr size_t OFF_EIDU = OFF_CURV + SZ_CNT;
static constexpr size_t OFF_EIDV = OFF_EIDU + SZ_EID;
static constexpr size_t OFF_RED  = OFF_EIDV + SZ_EID;
static constexpr size_t OFF_STAT = OFF_RED + SZ_RED;
static constexpr size_t SCRATCH_TOTAL = OFF_STAT + SZ_STAT;

__device__ __align__(256) unsigned char g_scratch[SCRATCH_TOTAL];

// stats region layout (float index into STAT block)
// 0:sum_u 256:ssq_u 512:sum_v 768:ssq_v 1024:sum_e 1088:ssq_e
// 1152:scale_u 1408:shift_u 1664:scale_v 1920:shift_v 2176:scale_e 2240:shift_e

__device__ __forceinline__ float*  SF(size_t off) { return (float*)(g_scratch + off); }
__device__ __forceinline__ int*    SI(size_t off) { return (int*)(g_scratch + off); }

// ---------------- init: zero counters & BN accumulators ----------------
__global__ void init_k() {
    int i = blockIdx.x * blockDim.x + threadIdx.x;
    int* cu = SI(OFF_CNTU);
    int* cv = SI(OFF_CNTV);
    float* st = SF(OFF_STAT);
    if (i < NU) { cu[i] = 0; cv[i] = 0; }
    if (i < 1152) st[i] = 0.f;
}

// ---------------- attention logits: one warp per row ----------------
__global__ void logits_k(const float* __restrict__ xus, const float* __restrict__ xvs,
                         const float* __restrict__ attn_u2v, const float* __restrict__ attn_v2u) {
    int w = (blockIdx.x * blockDim.x + threadIdx.x) >> 5;
    int lane = threadIdx.x & 31;
    if (w >= NU + NV) return;
    const float* x; const float* a; float* out; int r;
    if (w < NU) { x = xus; a = attn_u2v; out = SF(OFF_LU); r = w; }
    else        { x = xvs; a = attn_v2u; out = SF(OFF_LV); r = w - NU; }
    float s = 0.f;
    const float* xr = x + (size_t)r * 256;
    #pragma unroll
    for (int k = lane; k < 256; k += 32) s += xr[k] * a[k];
    #pragma unroll
    for (int o = 16; o; o >>= 1) s += __shfl_down_sync(0xffffffffu, s, o);
    if (lane == 0) out[r] = s;
}

// ---------------- global softmax reduce (max & sumexp), 2 blocks ----------------
__global__ void softmax_reduce_k() {
    const float* l = blockIdx.x ? SF(OFF_LV) : SF(OFF_LU);
    __shared__ float sh[1024];
    int t = threadIdx.x;
    float m = NEG_BIG;
    for (int i = t; i < NU; i += 1024) m = fmaxf(m, l[i]);
    sh[t] = m; __syncthreads();
    for (int s = 512; s; s >>= 1) { if (t < s) sh[t] = fmaxf(sh[t], sh[t + s]); __syncthreads(); }
    float mx = sh[0]; __syncthreads();
    float su = 0.f;
    for (int i = t; i < NU; i += 1024) su += expf(l[i] - mx);
    sh[t] = su; __syncthreads();
    for (int s = 512; s; s >>= 1) { if (t < s) sh[t] += sh[t + s]; __syncthreads(); }
    if (t == 0) { float* red = SF(OFF_RED); red[blockIdx.x * 2] = mx; red[blockIdx.x * 2 + 1] = sh[0]; }
}

__global__ void weights_k() {
    int i = blockIdx.x * blockDim.x + threadIdx.x;
    if (i >= NU) return;
    float* red = SF(OFF_RED);
    SF(OFF_WU)[i] = expf(SF(OFF_LU)[i] - red[0]) / red[1];
    SF(OFF_WV)[i] = expf(SF(OFF_LV)[i] - red[2]) / red[3];
}

// ---------------- CSR build ----------------
__global__ void hist_k(const int* __restrict__ row_v2u, const int* __restrict__ col_u2v) {
    int i = blockIdx.x * blockDim.x + threadIdx.x;
    if (i < NE) atomicAdd(&SI(OFF_CNTU)[row_v2u[i]], 1);
    else if (i < 2 * NE) atomicAdd(&SI(OFF_CNTV)[col_u2v[i - NE]], 1);
}

__global__ void scan_k() {
    const int* cnt = blockIdx.x ? SI(OFF_CNTV) : SI(OFF_CNTU);
    int* off = blockIdx.x ? SI(OFF_OFFV) : SI(OFF_OFFU);
    int* cur = blockIdx.x ? SI(OFF_CURV) : SI(OFF_CURU);
    __shared__ int sh[1024];
    __shared__ int carry;
    int t = threadIdx.x;
    if (t == 0) carry = 0;
    __syncthreads();
    for (int base = 0; base < NU; base += 1024) {
        int i = base + t;
        int v = (i < NU) ? cnt[i] : 0;
        sh[t] = v; __syncthreads();
        for (int s = 1; s < 1024; s <<= 1) {
            int tv = (t >= s) ? sh[t - s] : 0;
            __syncthreads();
            sh[t] += tv;
            __syncthreads();
        }
        int exc = sh[t] - v;
        if (i < NU) { off[i] = carry + exc; cur[i] = carry + exc; }
        __syncthreads();
        if (t == 0) carry += sh[1023];
        __syncthreads();
    }
    if (t == 0) off[NU] = carry;
}

__global__ void scatter_k(const int* __restrict__ row_v2u, const int* __restrict__ col_u2v) {
    int i = blockIdx.x * blockDim.x + threadIdx.x;
    if (i < NE) {
        int p = atomicAdd(&SI(OFF_CURU)[row_v2u[i]], 1);
        SI(OFF_EIDU)[p] = i;
    } else if (i < 2 * NE) {
        int e = i - NE;
        int p = atomicAdd(&SI(OFF_CURV)[col_u2v[e]], 1);
        SI(OFF_EIDV)[p] = e;
    }
}

// ---------------- aggregation: one block per destination node ----------------
// builds h row: [xtgt(256) | mean_msg(256) | max_msg(256) | mean_e(64) | max_e(64)]
__global__ __launch_bounds__(256) void agg_k(const int* __restrict__ off, const int* __restrict__ eids,
                      const int* __restrict__ src_of_e,
                      const float* __restrict__ w,
                      const float* __restrict__ xsrc,
                      const float* __restrict__ xe,
                      const float* __restrict__ xtgt,
                      float* __restrict__ h) {
    int u = blockIdx.x;
    int t = threadIdx.x;
    int s = off[u], e = off[u + 1];
    int deg = e - s;
    float sum = 0.f, mx = NEG_BIG, esum = 0.f, emx = NEG_BIG;
    for (int i = s; i < e; i++) {
        int eid = __ldg(&eids[i]);
        int src = __ldg(&src_of_e[eid]);
        float ww = __ldg(&w[src]);
        float v = ww * __ldg(&xsrc[(size_t)src * 256 + t]);
        sum += v;
        mx = fmaxf(mx, v);
        if (t < 64) {
            float ev = __ldg(&xe[(size_t)eid * 64 + t]);
            esum += ev;
            emx = fmaxf(emx, ev);
        }
    }
    float inv = 1.f / (float)(deg > 0 ? deg : 1);
    size_t base = (size_t)u * DU;
    h[base + t]       = xtgt[(size_t)u * 256 + t];
    h[base + 256 + t] = sum * inv;
    h[base + 512 + t] = (deg > 0) ? mx : 0.f;
    if (t < 64) {
        h[base + 768 + t] = esum * inv;
        h[base + 832 + t] = (deg > 0) ? emx : 0.f;
    }
}

// ---------------- tiled fp32 GEMM: C[M,N] = A[M,K] @ B[K,N] ----------------
// 64x64 block tile, 256 threads, 4x4 per thread, k-tile 16
__global__ __launch_bounds__(256) void gemm_k(const float* __restrict__ A, int lda,
                       const float* __restrict__ B, int ldb,
                       float* __restrict__ C, int ldc,
                       int M, int N, int K) {
    __shared__ float As[16][68];
    __shared__ float Bs[16][64];
    int tx = threadIdx.x & 15;
    int ty = threadIdx.x >> 4;
    int m0 = blockIdx.y * 64;
    int n0 = blockIdx.x * 64;
    int ar = threadIdx.x >> 2;
    int ak = (threadIdx.x & 3) * 4;
    int bk = threadIdx.x >> 4;
    int bn = (threadIdx.x & 15) * 4;
    float acc[4][4];
    #pragma unroll
    for (int i = 0; i < 4; i++)
        #pragma unroll
        for (int j = 0; j < 4; j++) acc[i][j] = 0.f;

    for (int k0 = 0; k0 < K; k0 += 16) {
        float4 av = make_float4(0.f, 0.f, 0.f, 0.f);
        int arow = m0 + ar;
        if (arow < M) av = *reinterpret_cast<const float4*>(&A[(size_t)arow * lda + k0 + ak]);
        As[ak + 0][ar] = av.x;
        As[ak + 1][ar] = av.y;
        As[ak + 2][ar] = av.z;
        As[ak + 3][ar] = av.w;
        float4 bv = *reinterpret_cast<const float4*>(&B[(size_t)(k0 + bk) * ldb + n0 + bn]);
        *reinterpret_cast<float4*>(&Bs[bk][bn]) = bv;
        __syncthreads();
        #pragma unroll
        for (int kk = 0; kk < 16; kk++) {
            float4 a = *reinterpret_cast<const float4*>(&As[kk][ty * 4]);
            float4 b = *reinterpret_cast<const float4*>(&Bs[kk][tx * 4]);
            float aa[4] = {a.x, a.y, a.z, a.w};
            float bb[4] = {b.x, b.y, b.z, b.w};
            #pragma unroll
            for (int i = 0; i < 4; i++)
                #pragma unroll
                for (int j = 0; j < 4; j++) acc[i][j] += aa[i] * bb[j];
        }
        __syncthreads();
    }
    #pragma unroll
    for (int i = 0; i < 4; i++) {
        int m = m0 + ty * 4 + i;
        if (m < M) {
            float4 v = make_float4(acc[i][0], acc[i][1], acc[i][2], acc[i][3]);
            *reinterpret_cast<float4*>(&C[(size_t)m * ldc + n0 + tx * 4]) = v;
        }
    }
}

// ---------------- edge combine: out_e += pu[row] + pv[col] ----------------
__global__ void combine_k(float* __restrict__ outE, const float* __restrict__ pu,
                          const float* __restrict__ pv,
                          const int* __restrict__ row_e, const int* __restrict__ col_e) {
    size_t total = (size_t)NE * 64;
    size_t stride = (size_t)gridDim.x * blockDim.x;
    for (size_t i = blockIdx.x * (size_t)blockDim.x + threadIdx.x; i < total; i += stride) {
        int e = (int)(i >> 6);
        int c = (int)(i & 63);
        int r = __ldg(&row_e[e]);
        int cc = __ldg(&col_e[e]);
        outE[i] += pu[(size_t)r * 64 + c] + pv[(size_t)cc * 64 + c];
    }
}

// ---------------- BN column stats (requires total threads % C == 0) ----------------
__global__ void colstats_k(const float* __restrict__ X, int M, int C,
                           float* __restrict__ sum, float* __restrict__ ssq) {
    size_t tid = blockIdx.x * (size_t)blockDim.x + threadIdx.x;
    size_t stride = (size_t)gridDim.x * blockDim.x;
    int c = (int)(tid % C);
    float s = 0.f, s2 = 0.f;
    size_t total = (size_t)M * C;
    for (size_t i = tid; i < total; i += stride) {
        float v = X[i];
        s += v; s2 += v * v;
    }
    atomicAdd(&sum[c], s);
    atomicAdd(&ssq[c], s2);
}

__global__ void bnfin_k(const float* __restrict__ sum, const float* __restrict__ ssq,
                        const float* __restrict__ g, const float* __restrict__ be,
                        float* __restrict__ scale, float* __restrict__ shift, int M, int C) {
    int c = blockIdx.x * blockDim.x + threadIdx.x;
    if (c >= C) return;
    float mu = sum[c] / (float)M;
    float var = ssq[c] / (float)M - mu * mu;
    float sc = g[c] * rsqrtf(var + BN_EPS);
    scale[c] = sc;
    shift[c] = be[c] - mu * sc;
}

__global__ void bnapply_k(float* __restrict__ X, size_t total, int C,
                          const float* __restrict__ scale, const float* __restrict__ shift) {
    size_t stride = (size_t)gridDim.x * blockDim.x;
    for (size_t i = blockIdx.x * (size_t)blockDim.x + threadIdx.x; i < total; i += stride) {
        int c = (int)(i % C);
        X[i] = X[i] * scale[c] + shift[c];
    }
}

// ---------------- launch ----------------
extern "C" void kernel_launch(void* const* d_in, const int* in_sizes, int n_in,
                              void* d_out, int out_size) {
    const float* xus     = (const float*)d_in[0];
    const float* xut     = (const float*)d_in[1];
    const float* xvs     = (const float*)d_in[2];
    const float* xvt     = (const float*)d_in[3];
    const float* xe_e    = (const float*)d_in[4];
    const float* xe_v2u  = (const float*)d_in[5];
    const float* xe_u2v  = (const float*)d_in[6];
    const int*   row_v2u = (const int*)d_in[7];
    const int*   col_v2u = (const int*)d_in[8];
    const int*   row_u2v = (const int*)d_in[9];
    const int*   col_u2v = (const int*)d_in[10];
    const int*   row_e   = (const int*)d_in[11];
    const int*   col_e   = (const int*)d_in[12];
    const float* attn_v2u = (const float*)d_in[13];
    const float* W_v2u    = (const float*)d_in[14];
    // b_v2u = d_in[15] (irrelevant: BN removes constant bias)
    const float* g_v2u    = (const float*)d_in[16];
    const float* be_v2u   = (const float*)d_in[17];
    const float* attn_u2v = (const float*)d_in[18];
    const float* W_u2v    = (const float*)d_in[19];
    const float* g_u2v    = (const float*)d_in[21];
    const float* be_u2v   = (const float*)d_in[22];
    const float* W_e      = (const float*)d_in[23];
    const float* g_e      = (const float*)d_in[25];
    const float* be_e     = (const float*)d_in[26];

    float* out_u = (float*)d_out;
    float* out_v = out_u + (size_t)NU * OU;
    float* out_e = out_v + (size_t)NV * OV;

    unsigned char* base = nullptr;
    cudaGetSymbolAddress((void**)&base, g_scratch);
    float* h_u = (float*)(base + OFF_HU);
    float* h_v = (float*)(base + OFF_HV);
    float* pu  = (float*)(base + OFF_PU);
    float* pv  = (float*)(base + OFF_PV);
    float* wu  = (float*)(base + OFF_WU);
    float* wv  = (float*)(base + OFF_WV);
    int* off_u = (int*)(base + OFF_OFFU);
    int* off_v = (int*)(base + OFF_OFFV);
    int* eid_u = (int*)(base + OFF_EIDU);
    int* eid_v = (int*)(base + OFF_EIDV);
    float* st  = (float*)(base + OFF_STAT);
    float* sum_u = st + 0,    *ssq_u = st + 256;
    float* sum_v = st + 512,  *ssq_v = st + 768;
    float* sum_e = st + 1024, *ssq_e = st + 1088;
    float* scale_u = st + 1152, *shift_u = st + 1408;
    float* scale_v = st + 1664, *shift_v = st + 1920;
    float* scale_e = st + 2176, *shift_e = st + 2240;

    // 1. init counters / BN accumulators
    init_k<<<(NU + 255) / 256, 256>>>();
    // 2. attention logits (warp per row)
    logits_k<<<(NU + NV) / 8, 256>>>(xus, xvs, attn_u2v, attn_v2u);
    // 3. global softmax reduce + weights
    softmax_reduce_k<<<2, 1024>>>();
    weights_k<<<(NU + 255) / 256, 256>>>();
    // 4. CSR build for both directions
    hist_k<<<(2 * NE + 255) / 256, 256>>>(row_v2u, col_u2v);
    scan_k<<<2, 1024>>>();
    scatter_k<<<(2 * NE + 255) / 256, 256>>>(row_v2u, col_u2v);
    // 5. segment mean/max aggregation -> h_u, h_v (with target-feature copy)
    agg_k<<<NU, 256>>>(off_u, eid_u, col_v2u, wv, xvs, xe_v2u, xut, h_u);
    agg_k<<<NV, 256>>>(off_v, eid_v, row_u2v, wu, xus, xe_u2v, xvt, h_v);
    // 6. GEMMs (bias skipped: BN-invariant)
    {
        dim3 g1(OU / 64, (NU + 63) / 64);
        gemm_k<<<g1, 256>>>(h_u, DU, W_v2u, OU, out_u, OU, NU, OU, DU);
        gemm_k<<<g1, 256>>>(h_v, DV, W_u2v, OV, out_v, OV, NV, OV, DV);
        dim3 g2(1, (NU + 63) / 64);
        gemm_k<<<g2, 256>>>(xut, 256, W_e + 64 * 64, 64, pu, 64, NU, 64, 256);
        gemm_k<<<g2, 256>>>(xvt, 256, W_e + 320 * 64, 64, pv, 64, NV, 64, 256);
        dim3 g3(1, NE / 64);
        gemm_k<<<g3, 256>>>(xe_e, 64, W_e, 64, out_e, 64, NE, 64, 64);
    }
    // 7. edge combine: out_e += pu[row_e] + pv[col_e]
    combine_k<<<4096, 256>>>(out_e, pu, pv, row_e, col_e);
    // 8. BatchNorm (stats -> finalize -> apply), in place on d_out
    colstats_k<<<512, 256>>>(out_u, NU, OU, sum_u, ssq_u);
    colstats_k<<<512, 256>>>(out_v, NV, OV, sum_v, ssq_v);
    colstats_k<<<512, 256>>>(out_e, NE, OE, sum_e, ssq_e);
    bnfin_k<<<1, 256>>>(sum_u, ssq_u, g_v2u, be_v2u, scale_u, shift_u, NU, OU);
    bnfin_k<<<1, 256>>>(sum_v, ssq_v, g_u2v, be_u2v, scale_v, shift_v, NV, OV);
    bnfin_k<<<1, 64>>>(sum_e, ssq_e, g_e, be_e, scale_e, shift_e, NE, OE);
    bnapply_k<<<2048, 256>>>(out_u, (size_t)NU * OU, OU, scale_u, shift_u);
    bnapply_k<<<2048, 256>>>(out_v, (size_t)NV * OV, OV, scale_v, shift_v);
    bnapply_k<<<4096, 256>>>(out_e, (size_t)NE * OE, OE, scale_e, shift_e);
}